// round 14
// baseline (speedup 1.0000x reference)
#include <cuda_runtime.h>
#include <math.h>

#define NB 2
#define NH 8
#define BH (NB*NH)
#define SQ 1024
#define DH 64
#define DM 512
#define FULLMASK 0xffffffffu

// ---------------- scratch (device globals) --------------------------------
__device__ float g_q[BH * SQ * DH];
__device__ float g_k[BH * SQ * DH];
__device__ float g_vt[BH * DH * SQ];              // V transposed: [bh][d][s]
__device__ float g_att[NB * SQ * DM];
__device__ float g_x[NB * SQ * DM];

// ---------------- tf32 mma helpers ----------------------------------------
__device__ __forceinline__ unsigned f2tf(float f) {
    unsigned u;
    asm("cvt.rna.tf32.f32 %0, %1;" : "=r"(u) : "f"(f));
    return u;
}
__device__ __forceinline__ void mma8(float c[4], const unsigned a[4], const unsigned b[2]) {
    asm volatile(
        "mma.sync.aligned.m16n8k8.row.col.f32.tf32.tf32.f32 "
        "{%0,%1,%2,%3}, {%4,%5,%6,%7}, {%8,%9}, {%0,%1,%2,%3};\n"
        : "+f"(c[0]), "+f"(c[1]), "+f"(c[2]), "+f"(c[3])
        : "r"(a[0]), "r"(a[1]), "r"(a[2]), "r"(a[3]), "r"(b[0]), "r"(b[1]));
}
// store one 8-elem k-group, pair-permuted: [k0,k4,k1,k5,k2,k6,k3,k7]
__device__ __forceinline__ void st_group(unsigned* dst, const float* src) {
    float4 lo = *(const float4*)src;
    float4 hi = *(const float4*)(src + 4);
    uint4 u0; u0.x = f2tf(lo.x); u0.y = f2tf(hi.x); u0.z = f2tf(lo.y); u0.w = f2tf(hi.y);
    uint4 u1; u1.x = f2tf(lo.z); u1.y = f2tf(hi.z); u1.z = f2tf(lo.w); u1.w = f2tf(hi.w);
    *(uint4*)dst = u0;
    *(uint4*)(dst + 4) = u1;
}
__device__ __forceinline__ void lda(unsigned a[4], const unsigned* S, int row,
                                    int stride, int off) {
    uint2 p0 = *(const uint2*)(S + row * stride + off);
    uint2 p1 = *(const uint2*)(S + (row + 8) * stride + off);
    a[0] = p0.x; a[1] = p1.x; a[2] = p0.y; a[3] = p1.y;
}
__device__ __forceinline__ void ldb(unsigned b[2], const unsigned* S, int row,
                                    int stride, int off) {
    uint2 q = *(const uint2*)(S + row * stride + off);
    b[0] = q.x; b[1] = q.y;
}
// sincos rel-pos table value: pos in [0,32], d in [0,64)
__device__ __forceinline__ float table_val(int pos, int d) {
    float freq = expf((float)(d & ~1) * (-logf(10000.0f) / (float)DH));
    float a = (float)pos * freq;
    return (d & 1) ? cosf(a) : sinf(a);
}

// ---------------- QKV GEMM: 64x128 tile, 256 thr (R10-measured best) ------
#define GE_ST 40
#define GQ_SMEM ((2*64*GE_ST + 2*128*GE_ST) * 4)
__global__ __launch_bounds__(256) void gemm_qkv(
    const float* __restrict__ A0, const float* __restrict__ A1,
    const float* __restrict__ A2,
    const float* __restrict__ W0, const float* __restrict__ W1,
    const float* __restrict__ W2,
    const float* __restrict__ bb0, const float* __restrict__ bb1,
    const float* __restrict__ bb2)
{
    extern __shared__ __align__(16) unsigned sm[];
    unsigned* Asb[2] = { sm, sm + 64 * GE_ST };
    unsigned* Bsb[2] = { sm + 2 * 64 * GE_ST, sm + 2 * 64 * GE_ST + 128 * GE_ST };

    int z = blockIdx.z;
    const float* A    = (z == 0) ? A0  : (z == 1) ? A1  : A2;
    const float* W    = (z == 0) ? W0  : (z == 1) ? W1  : W2;
    const float* bias = (z == 0) ? bb0 : (z == 1) ? bb1 : bb2;

    int m0 = blockIdx.y * 64, n0 = blockIdx.x * 128;
    int t = threadIdx.x, warp = t >> 5, lane = t & 31;
    int g = lane >> 2, t4 = lane & 3;
    int wm = (warp >> 2) * 32, wn = (warp & 3) * 32;

    int rowA = t >> 2, grpA = t & 3;
    float ra[8], rb2[2][8];

    float c[2][4][4];
#pragma unroll
    for (int i = 0; i < 2; i++)
#pragma unroll
        for (int j = 0; j < 4; j++)
#pragma unroll
            for (int e = 0; e < 4; e++) c[i][j][e] = 0.f;

    {
        const float* s = A + (size_t)(m0 + rowA) * DM + grpA * 8;
        *(float4*)&ra[0] = *(const float4*)s;
        *(float4*)&ra[4] = *(const float4*)(s + 4);
#pragma unroll
        for (int p = 0; p < 2; p++) {
            int f = t + p * 256, row = f >> 2, grp = f & 3;
            const float* sb = W + (size_t)(n0 + row) * DM + grp * 8;
            *(float4*)&rb2[p][0] = *(const float4*)sb;
            *(float4*)&rb2[p][4] = *(const float4*)(sb + 4);
        }
        st_group(Asb[0] + rowA * GE_ST + grpA * 8, ra);
#pragma unroll
        for (int p = 0; p < 2; p++) {
            int f = t + p * 256, row = f >> 2, grp = f & 3;
            st_group(Bsb[0] + row * GE_ST + grp * 8, rb2[p]);
        }
    }
    __syncthreads();

    for (int s0 = 0; s0 < 16; s0++) {
        int bi = s0 & 1;
        if (s0 < 15) {
            int k0 = (s0 + 1) * 32;
            const float* s = A + (size_t)(m0 + rowA) * DM + k0 + grpA * 8;
            *(float4*)&ra[0] = *(const float4*)s;
            *(float4*)&ra[4] = *(const float4*)(s + 4);
#pragma unroll
            for (int p = 0; p < 2; p++) {
                int f = t + p * 256, row = f >> 2, grp = f & 3;
                const float* sb = W + (size_t)(n0 + row) * DM + k0 + grp * 8;
                *(float4*)&rb2[p][0] = *(const float4*)sb;
                *(float4*)&rb2[p][4] = *(const float4*)(sb + 4);
            }
        }
#pragma unroll
        for (int kk = 0; kk < 32; kk += 8) {
            int off = kk + 2 * t4;
            unsigned a[2][4], b[4][2];
#pragma unroll
            for (int i = 0; i < 2; i++) lda(a[i], Asb[bi], wm + 16 * i + g, GE_ST, off);
#pragma unroll
            for (int j = 0; j < 4; j++) ldb(b[j], Bsb[bi], wn + 8 * j + g, GE_ST, off);
#pragma unroll
            for (int i = 0; i < 2; i++)
#pragma unroll
                for (int j = 0; j < 4; j++) mma8(c[i][j], a[i], b[j]);
        }
        if (s0 < 15) {
            st_group(Asb[bi ^ 1] + rowA * GE_ST + grpA * 8, ra);
#pragma unroll
            for (int p = 0; p < 2; p++) {
                int f = t + p * 256, row = f >> 2, grp = f & 3;
                st_group(Bsb[bi ^ 1] + row * GE_ST + grp * 8, rb2[p]);
            }
            __syncthreads();
        }
    }

    float2 bv[4];
#pragma unroll
    for (int j = 0; j < 4; j++)
        bv[j] = *(const float2*)&bias[n0 + wn + 8 * j + 2 * t4];

#pragma unroll
    for (int i = 0; i < 2; i++)
#pragma unroll
        for (int h = 0; h < 2; h++) {
            int m = m0 + wm + 16 * i + g + 8 * h;
#pragma unroll
            for (int j = 0; j < 4; j++) {
                int n = n0 + wn + 8 * j + 2 * t4;
                float2 o;
                o.x = c[i][j][2 * h]     + bv[j].x;
                o.y = c[i][j][2 * h + 1] + bv[j].y;
                int b_ = m >> 10, s = m & (SQ - 1);
                int head = n >> 6, d = n & 63;
                if (z == 2) {
                    float* vt = g_vt + ((size_t)(b_ * NH + head) * DH + d) * SQ + s;
                    vt[0] = o.x;
                    vt[SQ] = o.y;
                } else {
                    float* dst = (z == 0) ? g_q : g_k;
                    *(float2*)&dst[((size_t)(b_ * NH + head) * SQ + s) * DH + d] = o;
                }
            }
        }
}

// ---------------- Wo GEMM: 32x64 tile, 128 thr, 512 CTAs ------------------
#define GO_SMEM (2 * (32 + 64) * GE_ST * 4)
__global__ __launch_bounds__(128) void gemm_out(
    const float* __restrict__ W, const float* __restrict__ bias,
    const float* __restrict__ resid)
{
    extern __shared__ __align__(16) unsigned sm[];
    unsigned* Asb[2] = { sm, sm + 32 * GE_ST };
    unsigned* Bsb[2] = { sm + 2 * 32 * GE_ST, sm + 2 * 32 * GE_ST + 64 * GE_ST };

    const float* A = g_att;

    int m0 = blockIdx.y * 32, n0 = blockIdx.x * 64;
    int t = threadIdx.x, warp = t >> 5, lane = t & 31;
    int g = lane >> 2, t4 = lane & 3;
    int wm = (warp >> 1) * 16, wn = (warp & 1) * 32;

    int rowA = t >> 2, grpA = t & 3;        // 32 rows x 4 groups, one pass
    float ra[8], rb2[2][8];

    float c[4][4];
#pragma unroll
    for (int j = 0; j < 4; j++)
#pragma unroll
        for (int e = 0; e < 4; e++) c[j][e] = 0.f;

    {
        const float* s = A + (size_t)(m0 + rowA) * DM + grpA * 8;
        *(float4*)&ra[0] = *(const float4*)s;
        *(float4*)&ra[4] = *(const float4*)(s + 4);
#pragma unroll
        for (int p = 0; p < 2; p++) {
            int f = t + p * 128, row = f >> 2, grp = f & 3;
            const float* sb = W + (size_t)(n0 + row) * DM + grp * 8;
            *(float4*)&rb2[p][0] = *(const float4*)sb;
            *(float4*)&rb2[p][4] = *(const float4*)(sb + 4);
        }
        st_group(Asb[0] + rowA * GE_ST + grpA * 8, ra);
#pragma unroll
        for (int p = 0; p < 2; p++) {
            int f = t + p * 128, row = f >> 2, grp = f & 3;
            st_group(Bsb[0] + row * GE_ST + grp * 8, rb2[p]);
        }
    }
    __syncthreads();

    for (int s0 = 0; s0 < 16; s0++) {
        int bi = s0 & 1;
        if (s0 < 15) {
            int k0 = (s0 + 1) * 32;
            const float* s = A + (size_t)(m0 + rowA) * DM + k0 + grpA * 8;
            *(float4*)&ra[0] = *(const float4*)s;
            *(float4*)&ra[4] = *(const float4*)(s + 4);
#pragma unroll
            for (int p = 0; p < 2; p++) {
                int f = t + p * 128, row = f >> 2, grp = f & 3;
                const float* sb = W + (size_t)(n0 + row) * DM + k0 + grp * 8;
                *(float4*)&rb2[p][0] = *(const float4*)sb;
                *(float4*)&rb2[p][4] = *(const float4*)(sb + 4);
            }
        }
#pragma unroll
        for (int kk = 0; kk < 32; kk += 8) {
            int off = kk + 2 * t4;
            unsigned a[4], b[4][2];
            lda(a, Asb[bi], wm + g, GE_ST, off);
#pragma unroll
            for (int j = 0; j < 4; j++) ldb(b[j], Bsb[bi], wn + 8 * j + g, GE_ST, off);
#pragma unroll
            for (int j = 0; j < 4; j++) mma8(c[j], a, b[j]);
        }
        if (s0 < 15) {
            st_group(Asb[bi ^ 1] + rowA * GE_ST + grpA * 8, ra);
#pragma unroll
            for (int p = 0; p < 2; p++) {
                int f = t + p * 128, row = f >> 2, grp = f & 3;
                st_group(Bsb[bi ^ 1] + row * GE_ST + grp * 8, rb2[p]);
            }
            __syncthreads();
        }
    }

    float2 bv[4];
#pragma unroll
    for (int j = 0; j < 4; j++)
        bv[j] = *(const float2*)&bias[n0 + wn + 8 * j + 2 * t4];

#pragma unroll
    for (int h = 0; h < 2; h++) {
        int m = m0 + wm + g + 8 * h;
#pragma unroll
        for (int j = 0; j < 4; j++) {
            int n = n0 + wn + 8 * j + 2 * t4;
            float2 o;
            o.x = c[j][2 * h]     + bv[j].x;
            o.y = c[j][2 * h + 1] + bv[j].y;
            float2 r2 = *(const float2*)&resid[(size_t)m * DM + n];
            o.x += r2.x; o.y += r2.y;
            *(float2*)&g_x[(size_t)m * DM + n] = o;
        }
    }
}

// ---------------- fused flash attention, 256 thr / 8 warps ----------------
#define FQ 64
#define FK 128
#define QS_ST 72
#define KS_ST 72
#define PS_ST 136
#define VS_ST 136
#define OFF_Q 0
#define OFF_KP (OFF_Q + 64*QS_ST)          /* 4608  */
#define OFF_V  (OFF_KP + 128*KS_ST)        /* 13824 */
#define OFF_BAND (OFF_V + 64*VS_ST)        /* 22528 */
#define OFF_RB (OFF_BAND + 64*32)          /* 24576 */
#define OFF_PM (OFF_RB + 64*34)            /* 26752 */
#define OFF_PS (OFF_PM + 128)              /* 26880 */
#define OFF_ML (OFF_PS + 128)              /* 27008 */
#define FL_SMEM ((OFF_ML + 128) * 4)       /* 108544 B */

__global__ __launch_bounds__(256, 2) void flash_tc() {
    extern __shared__ __align__(16) unsigned sm[];
    unsigned* Qs  = sm + OFF_Q;
    unsigned* KPs = sm + OFF_KP;           // K tile tf32 / P tile tf32 (aliased)
    unsigned* Vs  = sm + OFF_V;            // V^T tile; table (prologue) aliased
    float* band = (float*)(sm + OFF_BAND); // raw diagonal-band scores [64][32]
    float* rbs  = (float*)(sm + OFF_RB);   // rel-bias [64][34] -> table [33][64]
    float* pm   = (float*)(sm + OFF_PM);   // partial max [64][2]
    float* ps   = (float*)(sm + OFF_PS);   // partial sum [64][2]
    float* ml   = (float*)(sm + OFF_ML);   // per-row {b0|m, l}

    // rank permutation: pair heavy+light CTAs on the same SM
    int bid = blockIdx.x;
    int r;
    if (bid >= 108 && bid < 148) r = bid - 108;
    else if (bid < 108)          r = 40 + bid;
    else                         r = 255 - (bid - 148);
    int qt = 15 - (r >> 4);
    int bh = r & 15;
    int q0 = qt * FQ;

    int t = threadIdx.x, warp = t >> 5, lane = t & 31;
    int g = lane >> 2, t4 = lane & 3;
    int half = warp & 1;
    int wm = (warp >> 1) * 16;
    int r0 = wm + g, r1 = wm + g + 8;

    const float* qp  = g_q + (size_t)bh * SQ * DH;
    const float* kp  = g_k + (size_t)bh * SQ * DH;
    const float* vtp = g_vt + (size_t)bh * DH * SQ;

    // prologue: Q (permuted tf32), inline-computed permuted table into Vs
#pragma unroll
    for (int p = 0; p < 2; p++) {
        int f = t + p * 256, row = f >> 3, grp = f & 7;
        st_group(Qs + row * QS_ST + grp * 8, qp + (size_t)(q0 + row) * DH + grp * 8);
    }
    for (int f = t; f < 33 * 8; f += 256) {
        int row = f >> 3, grp = f & 7;
        __align__(16) float vals[8];
#pragma unroll
        for (int dd = 0; dd < 8; dd++) vals[dd] = table_val(row, grp * 8 + dd);
        st_group(Vs + row * VS_ST + grp * 8, vals);
    }
    for (int f = t; f < 64 * 32; f += 256) band[f] = -1.0e30f;
    __syncthreads();

    // Q fragments: register-resident for the whole kernel
    unsigned qa[8][4];
#pragma unroll
    for (int kk8 = 0; kk8 < 8; kk8++)
        lda(qa[kk8], Qs, r0, QS_ST, kk8 * 8 + 2 * t4);

    // rb MMA: half-0 warps compute rbs[row][col] = Q_row . table_col, col<33
    if (half == 0) {
        float rc[5][4];
#pragma unroll
        for (int j = 0; j < 5; j++)
#pragma unroll
            for (int e = 0; e < 4; e++) rc[j][e] = 0.f;
#pragma unroll
        for (int kk8 = 0; kk8 < 8; kk8++)
#pragma unroll
            for (int j = 0; j < 5; j++) {
                unsigned b[2];
                ldb(b, Vs, 8 * j + g, VS_ST, kk8 * 8 + 2 * t4);
                mma8(rc[j], qa[kk8], b);
            }
#pragma unroll
        for (int j = 0; j < 5; j++)
#pragma unroll
            for (int e = 0; e < 4; e++) {
                int col = 8 * j + 2 * t4 + (e & 1);
                int rl = (e >> 1) ? r1 : r0;
                if (col < 33) rbs[rl * 34 + col] = rc[j][e];
            }
    }

    float m0 = -1.0e30f, m1 = -1.0e30f, l0 = 0.f, l1 = 0.f;
    float pv[4][4];
#pragma unroll
    for (int j = 0; j < 4; j++)
#pragma unroll
        for (int e = 0; e < 4; e++) pv[j][e] = 0.f;

    int nkt = (qt + 2) >> 1;
    for (int kt = 0; kt < nkt; kt++) {
        int kb = kt * FK;
        __syncthreads();   // prev P/V (and prologue table/rbs) phase done
        // load K tile [128][64] permuted
#pragma unroll
        for (int p = 0; p < 4; p++) {
            int f = t + p * 256, row = f >> 3, grp = f & 7;
            st_group(KPs + row * KS_ST + grp * 8, kp + (size_t)(kb + row) * DH + grp * 8);
        }
        // load V^T tile [64 d][128 k] permuted
#pragma unroll
        for (int p = 0; p < 4; p++) {
            int f = t + p * 256, row = f >> 4, grp = f & 15;
            st_group(Vs + row * VS_ST + grp * 8, vtp + (size_t)row * SQ + kb + grp * 8);
        }
        __syncthreads();

        // S = Q @ K^T : warp = 16 rows x 64 k (its half)
        float sacc[8][4];
#pragma unroll
        for (int j = 0; j < 8; j++)
#pragma unroll
            for (int e = 0; e < 4; e++) sacc[j][e] = 0.f;
#pragma unroll
        for (int kk = 0; kk < 8; kk++) {
#pragma unroll
            for (int j = 0; j < 8; j++) {
                unsigned b[2];
                ldb(b, KPs, half * 64 + 8 * j + g, KS_ST, kk * 8 + 2 * t4);
                mma8(sacc[j], qa[kk], b);
            }
        }

        // rel-bias + scale + causal mask + band capture
#pragma unroll
        for (int j = 0; j < 8; j++)
#pragma unroll
            for (int e = 0; e < 4; e++) {
                int rl = (e >> 1) ? r1 : r0;
                int k = kb + half * 64 + 8 * j + 2 * t4 + (e & 1);
                int q = q0 + rl;
                float s;
                if (k > q) s = -1.0e30f;
                else {
                    int ridx = k - q + 32;
                    if (ridx < 0) ridx = 0;
                    s = (sacc[j][e] + rbs[rl * 34 + ridx]) * 0.125f;
                    int bi2 = k - q + 31;
                    if (bi2 >= 0) band[rl * 32 + bi2] = s;
                }
                sacc[j][e] = s;
            }

        // own-half max + own-half exp-sum; single exchange barrier
        float hm0 = -1.0e30f, hm1 = -1.0e30f;
#pragma unroll
        for (int j = 0; j < 8; j++) {
            hm0 = fmaxf(hm0, fmaxf(sacc[j][0], sacc[j][1]));
            hm1 = fmaxf(hm1, fmaxf(sacc[j][2], sacc[j][3]));
        }
        hm0 = fmaxf(hm0, __shfl_xor_sync(FULLMASK, hm0, 1));
        hm0 = fmaxf(hm0, __shfl_xor_sync(FULLMASK, hm0, 2));
        hm1 = fmaxf(hm1, __shfl_xor_sync(FULLMASK, hm1, 1));
        hm1 = fmaxf(hm1, __shfl_xor_sync(FULLMASK, hm1, 2));
        float ts0 = 0.f, ts1 = 0.f;
#pragma unroll
        for (int j = 0; j < 8; j++) {
            float p0 = __expf(sacc[j][0] - hm0); sacc[j][0] = p0; ts0 += p0;
            float p1 = __expf(sacc[j][1] - hm0); sacc[j][1] = p1; ts0 += p1;
            float p2 = __expf(sacc[j][2] - hm1); sacc[j][2] = p2; ts1 += p2;
            float p3 = __expf(sacc[j][3] - hm1); sacc[j][3] = p3; ts1 += p3;
        }
        ts0 += __shfl_xor_sync(FULLMASK, ts0, 1);
        ts0 += __shfl_xor_sync(FULLMASK, ts0, 2);
        ts1 += __shfl_xor_sync(FULLMASK, ts1, 1);
        ts1 += __shfl_xor_sync(FULLMASK, ts1, 2);
        if (t4 == 0) {
            pm[r0 * 2 + half] = hm0; ps[r0 * 2 + half] = ts0;
            pm[r1 * 2 + half] = hm1; ps[r1 * 2 + half] = ts1;
        }
        __syncthreads();   // also guards: all S reads of K done before P write
        float hA0 = pm[r0 * 2], hB0 = pm[r0 * 2 + 1];
        float sA0 = ps[r0 * 2], sB0 = ps[r0 * 2 + 1];
        float hA1 = pm[r1 * 2], hB1 = pm[r1 * 2 + 1];
        float sA1 = ps[r1 * 2], sB1 = ps[r1 * 2 + 1];
        float mn0 = fmaxf(m0, fmaxf(hA0, hB0));
        float mn1 = fmaxf(m1, fmaxf(hA1, hB1));
        float sc0 = __expf(m0 - mn0), sc1 = __expf(m1 - mn1);
        l0 = l0 * sc0 + sA0 * __expf(hA0 - mn0) + sB0 * __expf(hB0 - mn0);
        l1 = l1 * sc1 + sA1 * __expf(hA1 - mn1) + sB1 * __expf(hB1 - mn1);
        float es0 = __expf(hm0 - mn0), es1 = __expf(hm1 - mn1);
        m0 = mn0; m1 = mn1;
#pragma unroll
        for (int j = 0; j < 4; j++) {
            pv[j][0] *= sc0; pv[j][1] *= sc0;
            pv[j][2] *= sc1; pv[j][3] *= sc1;
        }

        // write P quadrant (rows wm.., k half) pre-permuted tf32 into K alias
#pragma unroll
        for (int j = 0; j < 8; j++)
#pragma unroll
            for (int e = 0; e < 4; e++) {
                int rl = (e >> 1) ? r1 : r0;
                float es = (e >> 1) ? es1 : es0;
                int pos = 2 * t4 + (e & 1);
                int slot = 2 * (pos & 3) + (pos >> 2);
                KPs[rl * PS_ST + (half * 8 + j) * 8 + slot] = f2tf(sacc[j][e] * es);
            }
        __syncthreads();

        // PV accumulate: warp = 16 rows x 32 d (its half), full 128 k
#pragma unroll
        for (int ks = 0; ks < 16; ks++) {
            unsigned a[4];
            lda(a, KPs, r0, PS_ST, ks * 8 + 2 * t4);
#pragma unroll
            for (int j = 0; j < 4; j++) {
                unsigned b[2];
                ldb(b, Vs, half * 32 + 8 * j + g, VS_ST, ks * 8 + 2 * t4);
                mma8(pv[j], a, b);
            }
        }
    }

    // epilogue
    if (t4 == 0 && half == 0) {
        ml[2 * r0] = m0; ml[2 * r0 + 1] = l0;
        ml[2 * r1] = m1; ml[2 * r1 + 1] = l1;
    }
    __syncthreads();
    // inline table -> rbs buffer ([33][64]); band exp + bucket0 mass per row
    for (int f = t; f < 33 * 64; f += 256) {
        int pos = f >> 6, d = f & 63;
        rbs[f] = table_val(pos, d);
    }
    if (t < 64) {
        float m = ml[2 * t], l = ml[2 * t + 1];
        float s = 0.f;
#pragma unroll 8
        for (int jj = 0; jj < 32; jj++) {
            float p = __expf(band[t * 32 + jj] - m);
            band[t * 32 + jj] = p;
            s += p;
        }
        ml[2 * t] = 1.0f - s / l;
    }
    __syncthreads();

    int b_ = bh >> 3, head = bh & 7;
#pragma unroll
    for (int h = 0; h < 2; h++) {
        int rl = (h ? r1 : r0);
        float l = ml[2 * rl + 1], b0 = ml[2 * rl];
        float inv = 1.0f / l;
        float o[8];
#pragma unroll
        for (int j = 0; j < 4; j++) {
            o[2 * j] = pv[j][2 * h];
            o[2 * j + 1] = pv[j][2 * h + 1];
        }
#pragma unroll 8
        for (int jj = 0; jj < 32; jj++) {
            float pb = band[rl * 32 + jj];
#pragma unroll
            for (int j = 0; j < 4; j++) {
                int d = half * 32 + 8 * j + 2 * t4;
                float2 tv = *(const float2*)&rbs[(jj + 1) * 64 + d];
                o[2 * j] += pb * tv.x;
                o[2 * j + 1] += pb * tv.y;
            }
        }
#pragma unroll
        for (int j = 0; j < 4; j++) {
            int d = half * 32 + 8 * j + 2 * t4;
            float2 t0 = *(const float2*)&rbs[d];
            float2 ov = make_float2(o[2 * j] * inv + b0 * t0.x,
                                    o[2 * j + 1] * inv + b0 * t0.y);
            *(float2*)&g_att[((size_t)(b_ * SQ) + q0 + rl) * DM + head * DH + d] = ov;
        }
    }
}

// ---------------- layernorm (unbiased std, /(std+eps)) -------------------
__global__ void ln_kernel(const float* __restrict__ w, const float* __restrict__ bvec,
                          float* __restrict__ out) {
    int m = blockIdx.x;
    int t = threadIdx.x;
    const float4* x4 = (const float4*)(g_x + (size_t)m * DM);
    float4 v = x4[t];
    float s = v.x + v.y + v.z + v.w;
#pragma unroll
    for (int o = 16; o; o >>= 1) s += __shfl_xor_sync(FULLMASK, s, o);
    __shared__ float sh[4];
    if ((t & 31) == 0) sh[t >> 5] = s;
    __syncthreads();
    float mean = (sh[0] + sh[1] + sh[2] + sh[3]) * (1.0f / (float)DM);

    float dx = v.x - mean, dy = v.y - mean, dz = v.z - mean, dw = v.w - mean;
    float s2 = dx * dx + dy * dy + dz * dz + dw * dw;
#pragma unroll
    for (int o = 16; o; o >>= 1) s2 += __shfl_xor_sync(FULLMASK, s2, o);
    __syncthreads();
    if ((t & 31) == 0) sh[t >> 5] = s2;
    __syncthreads();
    float var = (sh[0] + sh[1] + sh[2] + sh[3]) * (1.0f / (float)(DM - 1));
    float inv = 1.0f / (sqrtf(var) + 1e-6f);

    float4 wv = ((const float4*)w)[t];
    float4 bb = ((const float4*)bvec)[t];
    float4 r;
    r.x = wv.x * dx * inv + bb.x;
    r.y = wv.y * dy * inv + bb.y;
    r.z = wv.z * dz * inv + bb.z;
    r.w = wv.w * dw * inv + bb.w;
    ((float4*)out)[(size_t)m * (DM / 4) + t] = r;
}

// ---------------- launch --------------------------------------------------
extern "C" void kernel_launch(void* const* d_in, const int* in_sizes, int n_in,
                              void* d_out, int out_size) {
    const float* query = (const float*)d_in[0];
    const float* key   = (const float*)d_in[1];
    const float* value = (const float*)d_in[2];
    const float* Wq = (const float*)d_in[3];
    const float* bq = (const float*)d_in[4];
    const float* Wk = (const float*)d_in[5];
    const float* bk = (const float*)d_in[6];
    const float* Wv = (const float*)d_in[7];
    const float* bv = (const float*)d_in[8];
    const float* Wo = (const float*)d_in[9];
    const float* bo = (const float*)d_in[10];
    const float* lnw = (const float*)d_in[11];
    const float* lnb = (const float*)d_in[12];
    float* out = (float*)d_out;

    cudaFuncSetAttribute(gemm_qkv, cudaFuncAttributeMaxDynamicSharedMemorySize,
                         GQ_SMEM);
    cudaFuncSetAttribute(gemm_out, cudaFuncAttributeMaxDynamicSharedMemorySize,
                         GO_SMEM);
    gemm_qkv<<<dim3(DM / 128, (NB * SQ) / 64, 3), 256, GQ_SMEM>>>(
        query, key, value, Wq, Wk, Wv, bq, bk, bv);

    cudaFuncSetAttribute(flash_tc, cudaFuncAttributeMaxDynamicSharedMemorySize,
                         FL_SMEM);
    flash_tc<<<256, 256, FL_SMEM>>>();

    gemm_out<<<dim3(DM / 64, (NB * SQ) / 32, 1), 128, GO_SMEM>>>(Wo, bo, query);

    ln_kernel<<<NB * SQ, 128>>>(lnw, lnb, out);
}

// round 15
// speedup vs baseline: 1.0439x; 1.0439x over previous
#include <cuda_runtime.h>
#include <math.h>

#define NB 2
#define NH 8
#define BH (NB*NH)
#define SQ 1024
#define DH 64
#define DM 512
#define FULLMASK 0xffffffffu

// ---------------- scratch (device globals) --------------------------------
__device__ float g_q[BH * SQ * DH];
__device__ float g_k[BH * SQ * DH];
__device__ float g_vt[BH * DH * SQ];              // V transposed: [bh][d][s]
__device__ float g_att[NB * SQ * DM];
__device__ float g_x[NB * SQ * DM];

// ---------------- tf32 mma helpers ----------------------------------------
__device__ __forceinline__ unsigned f2tf(float f) {
    unsigned u;
    asm("cvt.rna.tf32.f32 %0, %1;" : "=r"(u) : "f"(f));
    return u;
}
__device__ __forceinline__ void mma8(float c[4], const unsigned a[4], const unsigned b[2]) {
    asm volatile(
        "mma.sync.aligned.m16n8k8.row.col.f32.tf32.tf32.f32 "
        "{%0,%1,%2,%3}, {%4,%5,%6,%7}, {%8,%9}, {%0,%1,%2,%3};\n"
        : "+f"(c[0]), "+f"(c[1]), "+f"(c[2]), "+f"(c[3])
        : "r"(a[0]), "r"(a[1]), "r"(a[2]), "r"(a[3]), "r"(b[0]), "r"(b[1]));
}
// store one 8-elem k-group, pair-permuted: [k0,k4,k1,k5,k2,k6,k3,k7]
__device__ __forceinline__ void st_group(unsigned* dst, const float* src) {
    float4 lo = *(const float4*)src;
    float4 hi = *(const float4*)(src + 4);
    uint4 u0; u0.x = f2tf(lo.x); u0.y = f2tf(hi.x); u0.z = f2tf(lo.y); u0.w = f2tf(hi.y);
    uint4 u1; u1.x = f2tf(lo.z); u1.y = f2tf(hi.z); u1.z = f2tf(lo.w); u1.w = f2tf(hi.w);
    *(uint4*)dst = u0;
    *(uint4*)(dst + 4) = u1;
}
__device__ __forceinline__ void lda(unsigned a[4], const unsigned* S, int row,
                                    int stride, int off) {
    uint2 p0 = *(const uint2*)(S + row * stride + off);
    uint2 p1 = *(const uint2*)(S + (row + 8) * stride + off);
    a[0] = p0.x; a[1] = p1.x; a[2] = p0.y; a[3] = p1.y;
}
__device__ __forceinline__ void ldb(unsigned b[2], const unsigned* S, int row,
                                    int stride, int off) {
    uint2 q = *(const uint2*)(S + row * stride + off);
    b[0] = q.x; b[1] = q.y;
}
// sincos rel-pos table value: pos in [0,32], d in [0,64)
__device__ __forceinline__ float table_val(int pos, int d) {
    float freq = expf((float)(d & ~1) * (-logf(10000.0f) / (float)DH));
    float a = (float)pos * freq;
    return (d & 1) ? cosf(a) : sinf(a);
}

// ---------------- QKV GEMM: 64x128 tile, 256 thr (R10/R12-measured best) --
#define GE_ST 40
#define GQ_SMEM ((2*64*GE_ST + 2*128*GE_ST) * 4)
__global__ __launch_bounds__(256) void gemm_qkv(
    const float* __restrict__ A0, const float* __restrict__ A1,
    const float* __restrict__ A2,
    const float* __restrict__ W0, const float* __restrict__ W1,
    const float* __restrict__ W2,
    const float* __restrict__ bb0, const float* __restrict__ bb1,
    const float* __restrict__ bb2)
{
    extern __shared__ __align__(16) unsigned sm[];
    unsigned* Asb[2] = { sm, sm + 64 * GE_ST };
    unsigned* Bsb[2] = { sm + 2 * 64 * GE_ST, sm + 2 * 64 * GE_ST + 128 * GE_ST };

    int z = blockIdx.z;
    const float* A    = (z == 0) ? A0  : (z == 1) ? A1  : A2;
    const float* W    = (z == 0) ? W0  : (z == 1) ? W1  : W2;
    const float* bias = (z == 0) ? bb0 : (z == 1) ? bb1 : bb2;

    int m0 = blockIdx.y * 64, n0 = blockIdx.x * 128;
    int t = threadIdx.x, warp = t >> 5, lane = t & 31;
    int g = lane >> 2, t4 = lane & 3;
    int wm = (warp >> 2) * 32, wn = (warp & 3) * 32;

    int rowA = t >> 2, grpA = t & 3;
    float ra[8], rb2[2][8];

    float c[2][4][4];
#pragma unroll
    for (int i = 0; i < 2; i++)
#pragma unroll
        for (int j = 0; j < 4; j++)
#pragma unroll
            for (int e = 0; e < 4; e++) c[i][j][e] = 0.f;

    {
        const float* s = A + (size_t)(m0 + rowA) * DM + grpA * 8;
        *(float4*)&ra[0] = *(const float4*)s;
        *(float4*)&ra[4] = *(const float4*)(s + 4);
#pragma unroll
        for (int p = 0; p < 2; p++) {
            int f = t + p * 256, row = f >> 2, grp = f & 3;
            const float* sb = W + (size_t)(n0 + row) * DM + grp * 8;
            *(float4*)&rb2[p][0] = *(const float4*)sb;
            *(float4*)&rb2[p][4] = *(const float4*)(sb + 4);
        }
        st_group(Asb[0] + rowA * GE_ST + grpA * 8, ra);
#pragma unroll
        for (int p = 0; p < 2; p++) {
            int f = t + p * 256, row = f >> 2, grp = f & 3;
            st_group(Bsb[0] + row * GE_ST + grp * 8, rb2[p]);
        }
    }
    __syncthreads();

    for (int s0 = 0; s0 < 16; s0++) {
        int bi = s0 & 1;
        if (s0 < 15) {
            int k0 = (s0 + 1) * 32;
            const float* s = A + (size_t)(m0 + rowA) * DM + k0 + grpA * 8;
            *(float4*)&ra[0] = *(const float4*)s;
            *(float4*)&ra[4] = *(const float4*)(s + 4);
#pragma unroll
            for (int p = 0; p < 2; p++) {
                int f = t + p * 256, row = f >> 2, grp = f & 3;
                const float* sb = W + (size_t)(n0 + row) * DM + k0 + grp * 8;
                *(float4*)&rb2[p][0] = *(const float4*)sb;
                *(float4*)&rb2[p][4] = *(const float4*)(sb + 4);
            }
        }
#pragma unroll
        for (int kk = 0; kk < 32; kk += 8) {
            int off = kk + 2 * t4;
            unsigned a[2][4], b[4][2];
#pragma unroll
            for (int i = 0; i < 2; i++) lda(a[i], Asb[bi], wm + 16 * i + g, GE_ST, off);
#pragma unroll
            for (int j = 0; j < 4; j++) ldb(b[j], Bsb[bi], wn + 8 * j + g, GE_ST, off);
#pragma unroll
            for (int i = 0; i < 2; i++)
#pragma unroll
                for (int j = 0; j < 4; j++) mma8(c[i][j], a[i], b[j]);
        }
        if (s0 < 15) {
            st_group(Asb[bi ^ 1] + rowA * GE_ST + grpA * 8, ra);
#pragma unroll
            for (int p = 0; p < 2; p++) {
                int f = t + p * 256, row = f >> 2, grp = f & 3;
                st_group(Bsb[bi ^ 1] + row * GE_ST + grp * 8, rb2[p]);
            }
            __syncthreads();
        }
    }

    float2 bv[4];
#pragma unroll
    for (int j = 0; j < 4; j++)
        bv[j] = *(const float2*)&bias[n0 + wn + 8 * j + 2 * t4];

#pragma unroll
    for (int i = 0; i < 2; i++)
#pragma unroll
        for (int h = 0; h < 2; h++) {
            int m = m0 + wm + 16 * i + g + 8 * h;
#pragma unroll
            for (int j = 0; j < 4; j++) {
                int n = n0 + wn + 8 * j + 2 * t4;
                float2 o;
                o.x = c[i][j][2 * h]     + bv[j].x;
                o.y = c[i][j][2 * h + 1] + bv[j].y;
                int b_ = m >> 10, s = m & (SQ - 1);
                int head = n >> 6, d = n & 63;
                if (z == 2) {
                    float* vt = g_vt + ((size_t)(b_ * NH + head) * DH + d) * SQ + s;
                    vt[0] = o.x;
                    vt[SQ] = o.y;
                } else {
                    float* dst = (z == 0) ? g_q : g_k;
                    *(float2*)&dst[((size_t)(b_ * NH + head) * SQ + s) * DH + d] = o;
                }
            }
        }
}

// ---------------- Wo GEMM: 64x64 tile, 128 thr (R11/R12-measured best) ----
#define GO_SMEM (4 * 64 * GE_ST * 4)
__global__ __launch_bounds__(128) void gemm_out(
    const float* __restrict__ W, const float* __restrict__ bias,
    const float* __restrict__ resid)
{
    extern __shared__ __align__(16) unsigned sm[];
    unsigned* Asb[2] = { sm, sm + 64 * GE_ST };
    unsigned* Bsb[2] = { sm + 2 * 64 * GE_ST, sm + 3 * 64 * GE_ST };

    const float* A = g_att;

    int m0 = blockIdx.y * 64, n0 = blockIdx.x * 64;
    int t = threadIdx.x, warp = t >> 5, lane = t & 31;
    int g = lane >> 2, t4 = lane & 3;
    int wm = (warp >> 1) * 32, wn = (warp & 1) * 32;

    int rowA = t >> 2, grpA = t & 3;        // 32 rows x 4 groups per 128-thr pass
    float ra[2][8], rb2[2][8];

    float c[2][4][4];
#pragma unroll
    for (int i = 0; i < 2; i++)
#pragma unroll
        for (int j = 0; j < 4; j++)
#pragma unroll
            for (int e = 0; e < 4; e++) c[i][j][e] = 0.f;

    {
#pragma unroll
        for (int p = 0; p < 2; p++) {
            const float* s = A + (size_t)(m0 + rowA + p * 32) * DM + grpA * 8;
            *(float4*)&ra[p][0] = *(const float4*)s;
            *(float4*)&ra[p][4] = *(const float4*)(s + 4);
            const float* sb = W + (size_t)(n0 + rowA + p * 32) * DM + grpA * 8;
            *(float4*)&rb2[p][0] = *(const float4*)sb;
            *(float4*)&rb2[p][4] = *(const float4*)(sb + 4);
        }
#pragma unroll
        for (int p = 0; p < 2; p++) {
            st_group(Asb[0] + (rowA + p * 32) * GE_ST + grpA * 8, ra[p]);
            st_group(Bsb[0] + (rowA + p * 32) * GE_ST + grpA * 8, rb2[p]);
        }
    }
    __syncthreads();

    for (int s0 = 0; s0 < 16; s0++) {
        int bi = s0 & 1;
        if (s0 < 15) {
            int k0 = (s0 + 1) * 32;
#pragma unroll
            for (int p = 0; p < 2; p++) {
                const float* s = A + (size_t)(m0 + rowA + p * 32) * DM + k0 + grpA * 8;
                *(float4*)&ra[p][0] = *(const float4*)s;
                *(float4*)&ra[p][4] = *(const float4*)(s + 4);
                const float* sb = W + (size_t)(n0 + rowA + p * 32) * DM + k0 + grpA * 8;
                *(float4*)&rb2[p][0] = *(const float4*)sb;
                *(float4*)&rb2[p][4] = *(const float4*)(sb + 4);
            }
        }
#pragma unroll
        for (int kk = 0; kk < 32; kk += 8) {
            int off = kk + 2 * t4;
            unsigned a[2][4], b[4][2];
#pragma unroll
            for (int i = 0; i < 2; i++) lda(a[i], Asb[bi], wm + 16 * i + g, GE_ST, off);
#pragma unroll
            for (int j = 0; j < 4; j++) ldb(b[j], Bsb[bi], wn + 8 * j + g, GE_ST, off);
#pragma unroll
            for (int i = 0; i < 2; i++)
#pragma unroll
                for (int j = 0; j < 4; j++) mma8(c[i][j], a[i], b[j]);
        }
        if (s0 < 15) {
#pragma unroll
            for (int p = 0; p < 2; p++) {
                st_group(Asb[bi ^ 1] + (rowA + p * 32) * GE_ST + grpA * 8, ra[p]);
                st_group(Bsb[bi ^ 1] + (rowA + p * 32) * GE_ST + grpA * 8, rb2[p]);
            }
            __syncthreads();
        }
    }

    float2 bv[4];
#pragma unroll
    for (int j = 0; j < 4; j++)
        bv[j] = *(const float2*)&bias[n0 + wn + 8 * j + 2 * t4];

#pragma unroll
    for (int i = 0; i < 2; i++)
#pragma unroll
        for (int h = 0; h < 2; h++) {
            int m = m0 + wm + 16 * i + g + 8 * h;
#pragma unroll
            for (int j = 0; j < 4; j++) {
                int n = n0 + wn + 8 * j + 2 * t4;
                float2 o;
                o.x = c[i][j][2 * h]     + bv[j].x;
                o.y = c[i][j][2 * h + 1] + bv[j].y;
                float2 r2 = *(const float2*)&resid[(size_t)m * DM + n];
                o.x += r2.x; o.y += r2.y;
                *(float2*)&g_x[(size_t)m * DM + n] = o;
            }
        }
}

// ---------------- fused flash attention, 256 thr / 8 warps ----------------
#define FQ 64
#define FK 128
#define QS_ST 72
#define KS_ST 72
#define PS_ST 136
#define VS_ST 136
#define OFF_Q 0
#define OFF_KP (OFF_Q + 64*QS_ST)          /* 4608  */
#define OFF_V  (OFF_KP + 128*KS_ST)        /* 13824 */
#define OFF_BAND (OFF_V + 64*VS_ST)        /* 22528 */
#define OFF_RB (OFF_BAND + 64*32)          /* 24576 */
#define OFF_PM (OFF_RB + 64*34)            /* 26752 */
#define OFF_PS (OFF_PM + 128)              /* 26880 */
#define OFF_ML (OFF_PS + 128)              /* 27008 */
#define FL_SMEM ((OFF_ML + 128) * 4)       /* 108544 B */

__global__ __launch_bounds__(256, 2) void flash_tc() {
    extern __shared__ __align__(16) unsigned sm[];
    unsigned* Qs  = sm + OFF_Q;
    unsigned* KPs = sm + OFF_KP;           // K tile tf32 / P tile tf32 (aliased)
    unsigned* Vs  = sm + OFF_V;            // V^T tile; table (prologue) aliased
    float* band = (float*)(sm + OFF_BAND); // raw diagonal-band scores [64][32]
    float* rbs  = (float*)(sm + OFF_RB);   // rel-bias [64][34] -> table [33][64]
    float* pm   = (float*)(sm + OFF_PM);   // partial max [64][2]
    float* ps   = (float*)(sm + OFF_PS);   // partial sum [64][2]
    float* ml   = (float*)(sm + OFF_ML);   // per-row {b0|m, l}

    // rank permutation: pair heavy+light CTAs on the same SM
    int bid = blockIdx.x;
    int r;
    if (bid >= 108 && bid < 148) r = bid - 108;
    else if (bid < 108)          r = 40 + bid;
    else                         r = 255 - (bid - 148);
    int qt = 15 - (r >> 4);
    int bh = r & 15;
    int q0 = qt * FQ;

    int t = threadIdx.x, warp = t >> 5, lane = t & 31;
    int g = lane >> 2, t4 = lane & 3;
    int half = warp & 1;
    int wm = (warp >> 1) * 16;
    int r0 = wm + g, r1 = wm + g + 8;

    const float* qp  = g_q + (size_t)bh * SQ * DH;
    const float* kp  = g_k + (size_t)bh * SQ * DH;
    const float* vtp = g_vt + (size_t)bh * DH * SQ;

    // prologue: Q (permuted tf32), inline-computed permuted table into Vs
#pragma unroll
    for (int p = 0; p < 2; p++) {
        int f = t + p * 256, row = f >> 3, grp = f & 7;
        st_group(Qs + row * QS_ST + grp * 8, qp + (size_t)(q0 + row) * DH + grp * 8);
    }
    for (int f = t; f < 33 * 8; f += 256) {
        int row = f >> 3, grp = f & 7;
        __align__(16) float vals[8];
#pragma unroll
        for (int dd = 0; dd < 8; dd++) vals[dd] = table_val(row, grp * 8 + dd);
        st_group(Vs + row * VS_ST + grp * 8, vals);
    }
    for (int f = t; f < 64 * 32; f += 256) band[f] = -1.0e30f;
    __syncthreads();

    // Q fragments: register-resident for the whole kernel
    unsigned qa[8][4];
#pragma unroll
    for (int kk8 = 0; kk8 < 8; kk8++)
        lda(qa[kk8], Qs, r0, QS_ST, kk8 * 8 + 2 * t4);

    // rb MMA: half-0 warps compute rbs[row][col] = Q_row . table_col, col<33
    if (half == 0) {
        float rc[5][4];
#pragma unroll
        for (int j = 0; j < 5; j++)
#pragma unroll
            for (int e = 0; e < 4; e++) rc[j][e] = 0.f;
#pragma unroll
        for (int kk8 = 0; kk8 < 8; kk8++)
#pragma unroll
            for (int j = 0; j < 5; j++) {
                unsigned b[2];
                ldb(b, Vs, 8 * j + g, VS_ST, kk8 * 8 + 2 * t4);
                mma8(rc[j], qa[kk8], b);
            }
#pragma unroll
        for (int j = 0; j < 5; j++)
#pragma unroll
            for (int e = 0; e < 4; e++) {
                int col = 8 * j + 2 * t4 + (e & 1);
                int rl = (e >> 1) ? r1 : r0;
                if (col < 33) rbs[rl * 34 + col] = rc[j][e];
            }
    }

    float m0 = -1.0e30f, m1 = -1.0e30f, l0 = 0.f, l1 = 0.f;
    float pv[4][4];
#pragma unroll
    for (int j = 0; j < 4; j++)
#pragma unroll
        for (int e = 0; e < 4; e++) pv[j][e] = 0.f;

    int nkt = (qt + 2) >> 1;
    for (int kt = 0; kt < nkt; kt++) {
        int kb = kt * FK;
        __syncthreads();   // prev P/V (and prologue table/rbs) phase done
        // load K tile [128][64] permuted
#pragma unroll
        for (int p = 0; p < 4; p++) {
            int f = t + p * 256, row = f >> 3, grp = f & 7;
            st_group(KPs + row * KS_ST + grp * 8, kp + (size_t)(kb + row) * DH + grp * 8);
        }
        // load V^T tile [64 d][128 k] permuted
#pragma unroll
        for (int p = 0; p < 4; p++) {
            int f = t + p * 256, row = f >> 4, grp = f & 15;
            st_group(Vs + row * VS_ST + grp * 8, vtp + (size_t)row * SQ + kb + grp * 8);
        }
        __syncthreads();

        // S = Q @ K^T : warp = 16 rows x 64 k (its half)
        float sacc[8][4];
#pragma unroll
        for (int j = 0; j < 8; j++)
#pragma unroll
            for (int e = 0; e < 4; e++) sacc[j][e] = 0.f;
#pragma unroll
        for (int kk = 0; kk < 8; kk++) {
#pragma unroll
            for (int j = 0; j < 8; j++) {
                unsigned b[2];
                ldb(b, KPs, half * 64 + 8 * j + g, KS_ST, kk * 8 + 2 * t4);
                mma8(sacc[j], qa[kk], b);
            }
        }

        // rel-bias + scale + causal mask + band capture
#pragma unroll
        for (int j = 0; j < 8; j++)
#pragma unroll
            for (int e = 0; e < 4; e++) {
                int rl = (e >> 1) ? r1 : r0;
                int k = kb + half * 64 + 8 * j + 2 * t4 + (e & 1);
                int q = q0 + rl;
                float s;
                if (k > q) s = -1.0e30f;
                else {
                    int ridx = k - q + 32;
                    if (ridx < 0) ridx = 0;
                    s = (sacc[j][e] + rbs[rl * 34 + ridx]) * 0.125f;
                    int bi2 = k - q + 31;
                    if (bi2 >= 0) band[rl * 32 + bi2] = s;
                }
                sacc[j][e] = s;
            }

        // own-half max + own-half exp-sum; single exchange barrier
        float hm0 = -1.0e30f, hm1 = -1.0e30f;
#pragma unroll
        for (int j = 0; j < 8; j++) {
            hm0 = fmaxf(hm0, fmaxf(sacc[j][0], sacc[j][1]));
            hm1 = fmaxf(hm1, fmaxf(sacc[j][2], sacc[j][3]));
        }
        hm0 = fmaxf(hm0, __shfl_xor_sync(FULLMASK, hm0, 1));
        hm0 = fmaxf(hm0, __shfl_xor_sync(FULLMASK, hm0, 2));
        hm1 = fmaxf(hm1, __shfl_xor_sync(FULLMASK, hm1, 1));
        hm1 = fmaxf(hm1, __shfl_xor_sync(FULLMASK, hm1, 2));
        float ts0 = 0.f, ts1 = 0.f;
#pragma unroll
        for (int j = 0; j < 8; j++) {
            float p0 = __expf(sacc[j][0] - hm0); sacc[j][0] = p0; ts0 += p0;
            float p1 = __expf(sacc[j][1] - hm0); sacc[j][1] = p1; ts0 += p1;
            float p2 = __expf(sacc[j][2] - hm1); sacc[j][2] = p2; ts1 += p2;
            float p3 = __expf(sacc[j][3] - hm1); sacc[j][3] = p3; ts1 += p3;
        }
        ts0 += __shfl_xor_sync(FULLMASK, ts0, 1);
        ts0 += __shfl_xor_sync(FULLMASK, ts0, 2);
        ts1 += __shfl_xor_sync(FULLMASK, ts1, 1);
        ts1 += __shfl_xor_sync(FULLMASK, ts1, 2);
        if (t4 == 0) {
            pm[r0 * 2 + half] = hm0; ps[r0 * 2 + half] = ts0;
            pm[r1 * 2 + half] = hm1; ps[r1 * 2 + half] = ts1;
        }
        __syncthreads();   // also guards: all S reads of K done before P write
        float hA0 = pm[r0 * 2], hB0 = pm[r0 * 2 + 1];
        float sA0 = ps[r0 * 2], sB0 = ps[r0 * 2 + 1];
        float hA1 = pm[r1 * 2], hB1 = pm[r1 * 2 + 1];
        float sA1 = ps[r1 * 2], sB1 = ps[r1 * 2 + 1];
        float mn0 = fmaxf(m0, fmaxf(hA0, hB0));
        float mn1 = fmaxf(m1, fmaxf(hA1, hB1));
        float sc0 = __expf(m0 - mn0), sc1 = __expf(m1 - mn1);
        l0 = l0 * sc0 + sA0 * __expf(hA0 - mn0) + sB0 * __expf(hB0 - mn0);
        l1 = l1 * sc1 + sA1 * __expf(hA1 - mn1) + sB1 * __expf(hB1 - mn1);
        float es0 = __expf(hm0 - mn0), es1 = __expf(hm1 - mn1);
        m0 = mn0; m1 = mn1;
#pragma unroll
        for (int j = 0; j < 4; j++) {
            pv[j][0] *= sc0; pv[j][1] *= sc0;
            pv[j][2] *= sc1; pv[j][3] *= sc1;
        }

        // write P quadrant (rows wm.., k half) pre-permuted tf32 into K alias
#pragma unroll
        for (int j = 0; j < 8; j++)
#pragma unroll
            for (int e = 0; e < 4; e++) {
                int rl = (e >> 1) ? r1 : r0;
                float es = (e >> 1) ? es1 : es0;
                int pos = 2 * t4 + (e & 1);
                int slot = 2 * (pos & 3) + (pos >> 2);
                KPs[rl * PS_ST + (half * 8 + j) * 8 + slot] = f2tf(sacc[j][e] * es);
            }
        __syncthreads();

        // PV accumulate: warp = 16 rows x 32 d (its half), full 128 k
#pragma unroll
        for (int ks = 0; ks < 16; ks++) {
            unsigned a[4];
            lda(a, KPs, r0, PS_ST, ks * 8 + 2 * t4);
#pragma unroll
            for (int j = 0; j < 4; j++) {
                unsigned b[2];
                ldb(b, Vs, half * 32 + 8 * j + g, VS_ST, ks * 8 + 2 * t4);
                mma8(pv[j], a, b);
            }
        }
    }

    // epilogue
    if (t4 == 0 && half == 0) {
        ml[2 * r0] = m0; ml[2 * r0 + 1] = l0;
        ml[2 * r1] = m1; ml[2 * r1 + 1] = l1;
    }
    __syncthreads();
    // inline table -> rbs buffer ([33][64]); band exp + bucket0 mass per row
    for (int f = t; f < 33 * 64; f += 256) {
        int pos = f >> 6, d = f & 63;
        rbs[f] = table_val(pos, d);
    }
    if (t < 64) {
        float m = ml[2 * t], l = ml[2 * t + 1];
        float s = 0.f;
#pragma unroll 8
        for (int jj = 0; jj < 32; jj++) {
            float p = __expf(band[t * 32 + jj] - m);
            band[t * 32 + jj] = p;
            s += p;
        }
        ml[2 * t] = 1.0f - s / l;
    }
    __syncthreads();

    int b_ = bh >> 3, head = bh & 7;
#pragma unroll
    for (int h = 0; h < 2; h++) {
        int rl = (h ? r1 : r0);
        float l = ml[2 * rl + 1], b0 = ml[2 * rl];
        float inv = 1.0f / l;
        float o[8];
#pragma unroll
        for (int j = 0; j < 4; j++) {
            o[2 * j] = pv[j][2 * h];
            o[2 * j + 1] = pv[j][2 * h + 1];
        }
#pragma unroll 8
        for (int jj = 0; jj < 32; jj++) {
            float pb = band[rl * 32 + jj];
#pragma unroll
            for (int j = 0; j < 4; j++) {
                int d = half * 32 + 8 * j + 2 * t4;
                float2 tv = *(const float2*)&rbs[(jj + 1) * 64 + d];
                o[2 * j] += pb * tv.x;
                o[2 * j + 1] += pb * tv.y;
            }
        }
#pragma unroll
        for (int j = 0; j < 4; j++) {
            int d = half * 32 + 8 * j + 2 * t4;
            float2 t0 = *(const float2*)&rbs[d];
            float2 ov = make_float2(o[2 * j] * inv + b0 * t0.x,
                                    o[2 * j + 1] * inv + b0 * t0.y);
            *(float2*)&g_att[((size_t)(b_ * SQ) + q0 + rl) * DM + head * DH + d] = ov;
        }
    }
}

// ---------------- layernorm (unbiased std, /(std+eps)) -------------------
__global__ void ln_kernel(const float* __restrict__ w, const float* __restrict__ bvec,
                          float* __restrict__ out) {
    int m = blockIdx.x;
    int t = threadIdx.x;
    const float4* x4 = (const float4*)(g_x + (size_t)m * DM);
    float4 v = x4[t];
    float s = v.x + v.y + v.z + v.w;
#pragma unroll
    for (int o = 16; o; o >>= 1) s += __shfl_xor_sync(FULLMASK, s, o);
    __shared__ float sh[4];
    if ((t & 31) == 0) sh[t >> 5] = s;
    __syncthreads();
    float mean = (sh[0] + sh[1] + sh[2] + sh[3]) * (1.0f / (float)DM);

    float dx = v.x - mean, dy = v.y - mean, dz = v.z - mean, dw = v.w - mean;
    float s2 = dx * dx + dy * dy + dz * dz + dw * dw;
#pragma unroll
    for (int o = 16; o; o >>= 1) s2 += __shfl_xor_sync(FULLMASK, s2, o);
    __syncthreads();
    if ((t & 31) == 0) sh[t >> 5] = s2;
    __syncthreads();
    float var = (sh[0] + sh[1] + sh[2] + sh[3]) * (1.0f / (float)(DM - 1));
    float inv = 1.0f / (sqrtf(var) + 1e-6f);

    float4 wv = ((const float4*)w)[t];
    float4 bb = ((const float4*)bvec)[t];
    float4 r;
    r.x = wv.x * dx * inv + bb.x;
    r.y = wv.y * dy * inv + bb.y;
    r.z = wv.z * dz * inv + bb.z;
    r.w = wv.w * dw * inv + bb.w;
    ((float4*)out)[(size_t)m * (DM / 4) + t] = r;
}

// ---------------- launch --------------------------------------------------
extern "C" void kernel_launch(void* const* d_in, const int* in_sizes, int n_in,
                              void* d_out, int out_size) {
    const float* query = (const float*)d_in[0];
    const float* key   = (const float*)d_in[1];
    const float* value = (const float*)d_in[2];
    const float* Wq = (const float*)d_in[3];
    const float* bq = (const float*)d_in[4];
    const float* Wk = (const float*)d_in[5];
    const float* bk = (const float*)d_in[6];
    const float* Wv = (const float*)d_in[7];
    const float* bv = (const float*)d_in[8];
    const float* Wo = (const float*)d_in[9];
    const float* bo = (const float*)d_in[10];
    const float* lnw = (const float*)d_in[11];
    const float* lnb = (const float*)d_in[12];
    float* out = (float*)d_out;

    cudaFuncSetAttribute(gemm_qkv, cudaFuncAttributeMaxDynamicSharedMemorySize,
                         GQ_SMEM);
    cudaFuncSetAttribute(gemm_out, cudaFuncAttributeMaxDynamicSharedMemorySize,
                         GO_SMEM);
    gemm_qkv<<<dim3(DM / 128, (NB * SQ) / 64, 3), 256, GQ_SMEM>>>(
        query, key, value, Wq, Wk, Wv, bq, bk, bv);

    cudaFuncSetAttribute(flash_tc, cudaFuncAttributeMaxDynamicSharedMemorySize,
                         FL_SMEM);
    flash_tc<<<256, 256, FL_SMEM>>>();

    gemm_out<<<dim3(DM / 64, (NB * SQ) / 64, 1), 128, GO_SMEM>>>(Wo, bo, query);

    ln_kernel<<<NB * SQ, 128>>>(lnw, lnb, out);
}